// round 1
// baseline (speedup 1.0000x reference)
#include <cuda_runtime.h>
#include <math.h>

#define NN 20000
#define EE 320000
#define CC 64
#define ZZ 10
#define LLAYERS 2
#define HH 64
#define NBES 8

// ---------------- scratch (device globals; no allocation allowed) ----------------
__device__ float g_s[NN*CC];
__device__ float g_v[NN*3*CC];
__device__ float g_sup[NN*CC];
__device__ float g_vup[NN*3*CC];
__device__ float g_agg0[NN*CC];
__device__ float g_agg1[NN*3*CC];
__device__ float g_Y1[EE*3];
__device__ float g_feats[EE*NBES];

__device__ __forceinline__ float silu_f(float x){ return x * (1.0f/(1.0f + __expf(-x))); }

// ---------------- geometry: Y1 and radial features (once) ----------------
__global__ void k_geom(const float* __restrict__ pos, const float* __restrict__ shifts,
                       const int* __restrict__ eidx)
{
    int e = blockIdx.x*blockDim.x + threadIdx.x;
    if (e >= EE) return;
    int snd = eidx[e], rcv = eidx[EE + e];
    float vx = pos[rcv*3+0]-pos[snd*3+0]+shifts[e*3+0];
    float vy = pos[rcv*3+1]-pos[snd*3+1]+shifts[e*3+1];
    float vz = pos[rcv*3+2]-pos[snd*3+2]+shifts[e*3+2];
    float r = sqrtf(vx*vx+vy*vy+vz*vz);
    float inv = 1.0f/(r + 1e-9f);
    const float S3 = 1.7320508075688772f;
    g_Y1[e*3+0] = S3*vx*inv;
    g_Y1[e*3+1] = S3*vy*inv;
    g_Y1[e*3+2] = S3*vz*inv;
    float u = r * 0.2f;             // r / R_MAX
    float env = 0.0f;
    if (u < 1.0f) {
        float u2=u*u, u4=u2*u2, u6=u4*u2;
        env = 1.0f - 28.0f*u6 + 48.0f*u6*u - 21.0f*u6*u2;   // p=6 envelope
    }
    float pref = 0.6324555320336759f * inv * env;           // sqrt(2/5)/(r+eps)*env
    const float PI = 3.14159265358979323846f;
    #pragma unroll
    for (int k=1;k<=NBES;k++)
        g_feats[e*NBES + (k-1)] = pref * sinf((float)k * PI * u);
}

// ---------------- embedding: s = onehot @ W_embed ; v = 0 ----------------
__global__ void k_embed(const float* __restrict__ attrs, const float* __restrict__ Wemb)
{
    int idx = blockIdx.x*blockDim.x + threadIdx.x;
    if (idx >= NN*CC) return;
    int n = idx >> 6, c = idx & 63;
    float acc = 0.f;
    #pragma unroll
    for (int z=0; z<ZZ; z++) acc += __ldg(attrs + n*ZZ + z) * __ldg(Wemb + z*CC + c);
    g_s[idx] = acc;
    g_v[n*192 + c]       = 0.f;
    g_v[n*192 + 64 + c]  = 0.f;
    g_v[n*192 + 128 + c] = 0.f;
}

// ---------------- zero aggregation buffers ----------------
__global__ void k_zero()
{
    int idx = blockIdx.x*blockDim.x + threadIdx.x;
    int stride = gridDim.x*blockDim.x;
    for (int i=idx; i<NN*CC;   i+=stride) g_agg0[i]=0.f;
    for (int i=idx; i<NN*3*CC; i+=stride) g_agg1[i]=0.f;
}

// ---------------- per-node channel-mix: s_up, v_up ----------------
__global__ __launch_bounds__(256) void k_up(const float* __restrict__ Ws, const float* __restrict__ Wv)
{
    __shared__ float sWs[CC*CC], sWv[CC*CC];
    __shared__ float stg[8][256];
    int tid = threadIdx.x;
    for (int i=tid;i<CC*CC;i+=256){ sWs[i]=Ws[i]; sWv[i]=Wv[i]; }
    __syncthreads();
    int warp = tid>>5, lane = tid&31;
    for (int n = blockIdx.x*8 + warp; n < NN; n += gridDim.x*8) {
        stg[warp][lane]      = g_s[n*64+lane];
        stg[warp][lane+32]   = g_s[n*64+lane+32];
        #pragma unroll
        for (int j=lane; j<192; j+=32) stg[warp][64+j] = g_v[n*192+j];
        __syncwarp();
        float a0=0.f, a1=0.f, av[3][2]={};
        #pragma unroll 4
        for (int c=0;c<64;c++){
            float ws0=sWs[c*64+lane], ws1=sWs[c*64+lane+32];
            float wv0=sWv[c*64+lane], wv1=sWv[c*64+lane+32];
            float bs=stg[warp][c];
            a0 += bs*ws0; a1 += bs*ws1;
            #pragma unroll
            for (int i=0;i<3;i++){
                float bv = stg[warp][64+i*64+c];
                av[i][0]+=bv*wv0; av[i][1]+=bv*wv1;
            }
        }
        g_sup[n*64+lane]=a0; g_sup[n*64+lane+32]=a1;
        #pragma unroll
        for (int i=0;i<3;i++){
            g_vup[n*192+i*64+lane]=av[i][0];
            g_vup[n*192+i*64+lane+32]=av[i][1];
        }
        __syncwarp();
    }
}

// ---------------- edge kernel: radial MLP + messages + scatter ----------------
// 512 threads = 16 warps, 4 edges per warp. Lane owns channels {lane, lane+32},
// accumulating all 5 w-components per channel -> message phase needs no exchange.
#define EB 4
#define NWARP_E 16
#define EDGE_SMEM_FLOATS (NBES*HH + HH*HH + HH*5*CC + NWARP_E*(32+256+256))

__global__ __launch_bounds__(512,1) void k_edge(
    const float* __restrict__ RW1, const float* __restrict__ RW2, const float* __restrict__ RW3,
    const int* __restrict__ eidx)
{
    extern __shared__ float sm[];
    float* sW1 = sm;                   // 512
    float* sW2 = sW1 + NBES*HH;        // 4096
    float* sW3 = sW2 + HH*HH;          // 20480
    float* sStage = sW3 + HH*5*CC;     // 16 warps * 544
    int tid = threadIdx.x;
    for (int i=tid; i<NBES*HH; i+=blockDim.x) sW1[i]=RW1[i];
    for (int i=tid; i<HH*HH;   i+=blockDim.x) sW2[i]=RW2[i];
    for (int i=tid; i<HH*5*CC; i+=blockDim.x) sW3[i]=RW3[i];
    __syncthreads();
    int warp = tid>>5, lane = tid&31;
    float* sFeat = sStage + warp*544;  // [EB][8]
    float* sH1   = sFeat + 32;         // [EB][64]
    float* sH2   = sH1 + 256;          // [EB][64]
    int eBase = (blockIdx.x * NWARP_E + warp) * EB;

    // stage radial features (coalesced: lane = e*8+k)
    sFeat[lane] = g_feats[eBase*NBES + lane];
    __syncwarp();

    // ---- h1 = silu(feats @ RW1) ----
    {
        float acc[EB][2] = {};
        #pragma unroll
        for (int k=0;k<NBES;k++){
            float wa = sW1[k*HH+lane], wb = sW1[k*HH+lane+32];
            #pragma unroll
            for (int e=0;e<EB;e++){
                float f = sFeat[e*8+k];
                acc[e][0] += f*wa; acc[e][1] += f*wb;
            }
        }
        #pragma unroll
        for (int e=0;e<EB;e++){
            sH1[e*64+lane]    = silu_f(acc[e][0]);
            sH1[e*64+lane+32] = silu_f(acc[e][1]);
        }
    }
    __syncwarp();

    // ---- h2 = silu(h1 @ RW2) ----
    {
        float acc[EB][2] = {};
        #pragma unroll 8
        for (int d=0;d<HH;d++){
            float wa = sW2[d*HH+lane], wb = sW2[d*HH+lane+32];
            #pragma unroll
            for (int e=0;e<EB;e++){
                float h = sH1[e*64+d];
                acc[e][0] += h*wa; acc[e][1] += h*wb;
            }
        }
        #pragma unroll
        for (int e=0;e<EB;e++){
            sH2[e*64+lane]    = silu_f(acc[e][0]);
            sH2[e*64+lane+32] = silu_f(acc[e][1]);
        }
    }
    __syncwarp();

    // ---- w = h2 @ RW3  (lane owns channels lane, lane+32; all 5 groups) ----
    float wacc[EB][5][2] = {};
    #pragma unroll 4
    for (int d=0;d<HH;d++){
        float hh[EB];
        #pragma unroll
        for (int e=0;e<EB;e++) hh[e] = sH2[e*64+d];
        #pragma unroll
        for (int g=0; g<5; g++){
            float wa = sW3[d*320 + g*64 + lane];
            float wb = sW3[d*320 + g*64 + lane + 32];
            #pragma unroll
            for (int e=0;e<EB;e++){
                wacc[e][g][0] += hh[e]*wa;
                wacc[e][g][1] += hh[e]*wb;
            }
        }
    }

    // ---- messages + scatter ----
    const float IS3 = 0.5773502691896258f;   // 1/sqrt(3)
    const float IS2 = 0.7071067811865475f;   // 1/sqrt(2)
    const float INV_AVG = 1.0f/32.0f;
    #pragma unroll
    for (int e=0;e<EB;e++){
        int eg = eBase + e;
        int snd = __ldg(eidx + eg);
        int rcv = __ldg(eidx + EE + eg);
        float y0 = __ldg(g_Y1 + eg*3 + 0);
        float y1 = __ldg(g_Y1 + eg*3 + 1);
        float y2 = __ldg(g_Y1 + eg*3 + 2);
        #pragma unroll
        for (int h=0; h<2; h++){
            int c = lane + h*32;
            float sj = __ldg(g_sup + snd*64 + c);
            float v0 = __ldg(g_vup + snd*192 + c);
            float v1 = __ldg(g_vup + snd*192 + 64 + c);
            float v2 = __ldg(g_vup + snd*192 + 128 + c);
            float w00  = wacc[e][0][h], w110 = wacc[e][1][h];
            float w011 = wacc[e][2][h], w101 = wacc[e][3][h], w111 = wacc[e][4][h];
            float dv = v0*y0 + v1*y1 + v2*y2;
            float m0 = w00*sj + w110*dv*IS3;
            float cx = v1*y2 - v2*y1;
            float cy = v2*y0 - v0*y2;
            float cz = v0*y1 - v1*y0;
            float sy = w011*sj;
            float w111s = w111*IS2;
            float m1x = sy*y0 + w101*v0 + w111s*cx;
            float m1y = sy*y1 + w101*v1 + w111s*cy;
            float m1z = sy*y2 + w101*v2 + w111s*cz;
            atomicAdd(g_agg0 + rcv*64 + c,        m0 *INV_AVG);
            atomicAdd(g_agg1 + rcv*192 + c,       m1x*INV_AVG);
            atomicAdd(g_agg1 + rcv*192 + 64 + c,  m1y*INV_AVG);
            atomicAdd(g_agg1 + rcv*192 + 128 + c, m1z*INV_AVG);
        }
    }
}

// ---------------- node update: out/sc/prod + write descriptor ----------------
#define NODE_SMEM_FLOATS (4*CC*CC + 8*768)

__global__ __launch_bounds__(256) void k_node(
    const float* __restrict__ attrs,
    const float* __restrict__ Wout_s, const float* __restrict__ Wout_v,
    const float* __restrict__ Wsc_s,  const float* __restrict__ Wsc_v,   // layer-resolved bases [Z][C][C]
    const float* __restrict__ P0,     const float* __restrict__ P1,      // layer-resolved [Z][C][3],[Z][C][2]
    const float* __restrict__ Wprod_s,const float* __restrict__ Wprod_v,
    float* __restrict__ outL)                                            // out + layer*64
{
    extern __shared__ float sm[];
    float* sWos = sm;
    float* sWov = sWos + 4096;
    float* sWps = sWov + 4096;
    float* sWpv = sWps + 4096;
    float* sStage = sWpv + 4096;
    int tid = threadIdx.x;
    for (int i=tid;i<4096;i+=blockDim.x){
        sWos[i]=Wout_s[i]; sWov[i]=Wout_v[i]; sWps[i]=Wprod_s[i]; sWpv[i]=Wprod_v[i];
    }
    __syncthreads();
    int warp = tid>>5, lane = tid&31;
    float* stg = sStage + warp*768;
    // stage layout: agg0 [0,64)  agg1 [64,256)  s [256,320)  v [320,512)  prodS [512,576)  prodV [576,768)

    for (int n = blockIdx.x*8 + warp; n < NN; n += gridDim.x*8) {
        float av = (lane < ZZ) ? __ldg(attrs + n*ZZ + lane) : 0.f;
        unsigned msk = __ballot_sync(0xffffffffu, av > 0.5f);
        int z = __ffs(msk) - 1;

        stg[lane]        = g_agg0[n*64+lane];
        stg[lane+32]     = g_agg0[n*64+lane+32];
        #pragma unroll
        for (int j=lane;j<192;j+=32) stg[64+j]  = g_agg1[n*192+j];
        stg[256+lane]    = g_s[n*64+lane];
        stg[256+lane+32] = g_s[n*64+lane+32];
        #pragma unroll
        for (int j=lane;j<192;j+=32) stg[320+j] = g_v[n*192+j];
        __syncwarp();

        const float* Wss = Wsc_s + (size_t)z*4096;
        const float* Wsv = Wsc_v + (size_t)z*4096;
        float ms0=0.f, ms1=0.f, scs0=0.f, scs1=0.f;
        float mv[3][2]={}, scv[3][2]={};
        #pragma unroll 4
        for (int c=0;c<64;c++){
            float a0 = stg[c];
            float sb = stg[256+c];
            float wos0=sWos[c*64+lane], wos1=sWos[c*64+lane+32];
            float wov0=sWov[c*64+lane], wov1=sWov[c*64+lane+32];
            float wss0=__ldg(Wss+c*64+lane), wss1=__ldg(Wss+c*64+lane+32);
            float wsv0=__ldg(Wsv+c*64+lane), wsv1=__ldg(Wsv+c*64+lane+32);
            ms0 += a0*wos0; ms1 += a0*wos1;
            scs0 += sb*wss0; scs1 += sb*wss1;
            #pragma unroll
            for (int i=0;i<3;i++){
                float a1 = stg[64+i*64+c];
                float vb = stg[320+i*64+c];
                mv[i][0]  += a1*wov0; mv[i][1]  += a1*wov1;
                scv[i][0] += vb*wsv0; scv[i][1] += vb*wsv1;
            }
        }

        const float* p0 = P0 + (size_t)z*CC*3;
        const float* q0 = P1 + (size_t)z*CC*2;
        float pa0=__ldg(p0+lane*3+0), pa1=__ldg(p0+lane*3+1), pa2=__ldg(p0+lane*3+2);
        float pb0=__ldg(p0+(lane+32)*3+0), pb1=__ldg(p0+(lane+32)*3+1), pb2=__ldg(p0+(lane+32)*3+2);
        float qa0=__ldg(q0+lane*2+0), qa1=__ldg(q0+lane*2+1);
        float qb0=__ldg(q0+(lane+32)*2+0), qb1=__ldg(q0+(lane+32)*2+1);

        float n2a = mv[0][0]*mv[0][0]+mv[1][0]*mv[1][0]+mv[2][0]*mv[2][0];
        float n2b = mv[0][1]*mv[0][1]+mv[1][1]*mv[1][1]+mv[2][1]*mv[2][1];
        stg[512+lane]    = pa0*ms0 + pa1*ms0*ms0 + pa2*n2a;
        stg[512+lane+32] = pb0*ms1 + pb1*ms1*ms1 + pb2*n2b;
        #pragma unroll
        for (int i=0;i<3;i++){
            stg[576+i*64+lane]    = qa0*mv[i][0] + qa1*ms0*mv[i][0];
            stg[576+i*64+lane+32] = qb0*mv[i][1] + qb1*ms1*mv[i][1];
        }
        __syncwarp();

        float sn0=scs0, sn1=scs1;
        float vn[3][2];
        #pragma unroll
        for (int i=0;i<3;i++){ vn[i][0]=scv[i][0]; vn[i][1]=scv[i][1]; }
        #pragma unroll 4
        for (int c=0;c<64;c++){
            float ps = stg[512+c];
            float wps0=sWps[c*64+lane], wps1=sWps[c*64+lane+32];
            float wpv0=sWpv[c*64+lane], wpv1=sWpv[c*64+lane+32];
            sn0 += ps*wps0; sn1 += ps*wps1;
            #pragma unroll
            for (int i=0;i<3;i++){
                float pv = stg[576+i*64+c];
                vn[i][0]+=pv*wpv0; vn[i][1]+=pv*wpv1;
            }
        }

        g_s[n*64+lane]=sn0; g_s[n*64+lane+32]=sn1;
        #pragma unroll
        for (int i=0;i<3;i++){
            g_v[n*192+i*64+lane]=vn[i][0];
            g_v[n*192+i*64+lane+32]=vn[i][1];
        }
        outL[n*128+lane]=sn0; outL[n*128+lane+32]=sn1;
        __syncwarp();
    }
}

// ---------------- launch ----------------
extern "C" void kernel_launch(void* const* d_in, const int* in_sizes, int n_in,
                              void* d_out, int out_size)
{
    const float* attrs   = (const float*)d_in[0];
    const float* pos     = (const float*)d_in[1];
    const float* shifts  = (const float*)d_in[2];
    const float* Wemb    = (const float*)d_in[3];
    const float* Wup_s   = (const float*)d_in[4];
    const float* Wup_v   = (const float*)d_in[5];
    const float* RW1     = (const float*)d_in[6];
    const float* RW2     = (const float*)d_in[7];
    const float* RW3     = (const float*)d_in[8];
    const float* Wout_s  = (const float*)d_in[9];
    const float* Wout_v  = (const float*)d_in[10];
    const float* Wsc_s   = (const float*)d_in[11];
    const float* Wsc_v   = (const float*)d_in[12];
    const float* P0      = (const float*)d_in[13];
    const float* P1      = (const float*)d_in[14];
    const float* Wprod_s = (const float*)d_in[15];
    const float* Wprod_v = (const float*)d_in[16];
    const int*   eidx    = (const int*)d_in[17];
    float* out = (float*)d_out;

    const int edge_smem = EDGE_SMEM_FLOATS * 4;
    const int node_smem = NODE_SMEM_FLOATS * 4;
    cudaFuncSetAttribute(k_edge, cudaFuncAttributeMaxDynamicSharedMemorySize, edge_smem);
    cudaFuncSetAttribute(k_node, cudaFuncAttributeMaxDynamicSharedMemorySize, node_smem);

    k_geom<<<(EE+255)/256, 256>>>(pos, shifts, eidx);
    k_embed<<<(NN*CC+255)/256, 256>>>(attrs, Wemb);

    for (int layer=0; layer<LLAYERS; layer++){
        k_zero<<<1024, 256>>>();
        k_up<<<592, 256>>>(Wup_s + layer*CC*CC, Wup_v + layer*CC*CC);
        k_edge<<<EE/(NWARP_E*EB), 512, edge_smem>>>(
            RW1 + layer*NBES*HH, RW2 + layer*HH*HH, RW3 + layer*HH*5*CC, eidx);
        k_node<<<296, 256, node_smem>>>(
            attrs,
            Wout_s + layer*CC*CC, Wout_v + layer*CC*CC,
            Wsc_s + (size_t)layer*ZZ*CC*CC, Wsc_v + (size_t)layer*ZZ*CC*CC,
            P0 + (size_t)layer*ZZ*CC*3, P1 + (size_t)layer*ZZ*CC*2,
            Wprod_s + layer*CC*CC, Wprod_v + layer*CC*CC,
            out + layer*CC);
    }
}

// round 2
// speedup vs baseline: 1.9418x; 1.9418x over previous
#include <cuda_runtime.h>
#include <math.h>

#define NN 20000
#define EE 320000
#define CC 64
#define ZZ 10
#define LLAYERS 2
#define HH 64
#define NBES 8
#define TT 4096

// ---------------- scratch (device globals; no allocation allowed) ----------------
__device__ float  g_s[NN*CC];
__device__ float  g_v[NN*3*CC];
__device__ float4 g_up[NN*CC];                 // (s_up, vx, vy, vz)
__device__ float4 g_agg[NN*CC];                // (agg0, a1x, a1y, a1z)
__device__ float4 g_Y1u[EE];                   // (y0, y1, y2, u)
__device__ float  g_tab[LLAYERS][TT*5*CC];     // w(u) table per layer

__device__ __forceinline__ float silu_f(float x){ return x * (1.0f/(1.0f + __expf(-x))); }

// ---------------- geometry: Y1 and normalized length (once) ----------------
__global__ void k_geom(const float* __restrict__ pos, const float* __restrict__ shifts,
                       const int* __restrict__ eidx)
{
    int e = blockIdx.x*blockDim.x + threadIdx.x;
    if (e >= EE) return;
    int snd = eidx[e], rcv = eidx[EE + e];
    float vx = pos[rcv*3+0]-pos[snd*3+0]+shifts[e*3+0];
    float vy = pos[rcv*3+1]-pos[snd*3+1]+shifts[e*3+1];
    float vz = pos[rcv*3+2]-pos[snd*3+2]+shifts[e*3+2];
    float r = sqrtf(vx*vx+vy*vy+vz*vz);
    float inv = 1.0f/(r + 1e-9f);
    const float S3 = 1.7320508075688772f;
    g_Y1u[e] = make_float4(S3*vx*inv, S3*vy*inv, S3*vz*inv, r*0.2f);
}

// ---------------- radial MLP table: w(u) for TT grid points, per layer ----------------
__global__ void k_table(const float* __restrict__ RW1, const float* __restrict__ RW2,
                        const float* __restrict__ RW3)
{
    int i = blockIdx.x;              // table row
    int l = blockIdx.y;              // layer
    int t = threadIdx.x;             // 64 threads
    const float* W1 = RW1 + l*NBES*HH;
    const float* W2 = RW2 + l*HH*HH;
    const float* W3 = RW3 + l*HH*5*CC;
    __shared__ float feats[NBES], h1[HH], h2[HH];

    if (t < NBES) {
        float u = (float)i / (float)(TT-1);
        float r = 5.0f*u;
        float inv = 1.0f/(r + 1e-9f);
        float env = 0.0f;
        if (u < 1.0f) {
            float u2=u*u, u4=u2*u2, u6=u4*u2;
            env = 1.0f - 28.0f*u6 + 48.0f*u6*u - 21.0f*u6*u2;
        }
        float pref = 0.6324555320336759f * inv * env;
        const float PI = 3.14159265358979323846f;
        feats[t] = pref * sinf((float)(t+1) * PI * u);
    }
    __syncthreads();
    float a = 0.f;
    #pragma unroll
    for (int k=0;k<NBES;k++) a += feats[k]*W1[k*HH+t];
    h1[t] = silu_f(a);
    __syncthreads();
    a = 0.f;
    #pragma unroll 8
    for (int d=0;d<HH;d++) a += h1[d]*W2[d*HH+t];
    h2[t] = silu_f(a);
    __syncthreads();
    float o[5] = {};
    #pragma unroll 8
    for (int d=0;d<HH;d++){
        float h = h2[d];
        #pragma unroll
        for (int g=0;g<5;g++) o[g] += h*W3[d*320 + g*64 + t];
    }
    #pragma unroll
    for (int g=0;g<5;g++) g_tab[l][i*320 + g*64 + t] = o[g];
}

// ---------------- embedding: s = onehot @ W_embed ; v = 0 ----------------
__global__ void k_embed(const float* __restrict__ attrs, const float* __restrict__ Wemb)
{
    int idx = blockIdx.x*blockDim.x + threadIdx.x;
    if (idx >= NN*CC) return;
    int n = idx >> 6, c = idx & 63;
    float acc = 0.f;
    #pragma unroll
    for (int z=0; z<ZZ; z++) acc += __ldg(attrs + n*ZZ + z) * __ldg(Wemb + z*CC + c);
    g_s[idx] = acc;
    g_v[n*192 + c]       = 0.f;
    g_v[n*192 + 64 + c]  = 0.f;
    g_v[n*192 + 128 + c] = 0.f;
}

// ---------------- zero aggregation buffer ----------------
__global__ void k_zero()
{
    int idx = blockIdx.x*blockDim.x + threadIdx.x;
    int stride = gridDim.x*blockDim.x;
    float4 z4 = make_float4(0.f,0.f,0.f,0.f);
    for (int i=idx; i<NN*CC; i+=stride) g_agg[i] = z4;
}

// ---------------- per-node channel-mix: s_up, v_up -> packed float4 ----------------
__global__ __launch_bounds__(256) void k_up(const float* __restrict__ Ws, const float* __restrict__ Wv)
{
    __shared__ float sWs[CC*CC], sWv[CC*CC];
    __shared__ float stg[8][256];
    int tid = threadIdx.x;
    for (int i=tid;i<CC*CC;i+=256){ sWs[i]=Ws[i]; sWv[i]=Wv[i]; }
    __syncthreads();
    int warp = tid>>5, lane = tid&31;
    for (int n = blockIdx.x*8 + warp; n < NN; n += gridDim.x*8) {
        stg[warp][lane]      = g_s[n*64+lane];
        stg[warp][lane+32]   = g_s[n*64+lane+32];
        #pragma unroll
        for (int j=lane; j<192; j+=32) stg[warp][64+j] = g_v[n*192+j];
        __syncwarp();
        float a0=0.f, a1=0.f, av[3][2]={};
        #pragma unroll 4
        for (int c=0;c<64;c++){
            float ws0=sWs[c*64+lane], ws1=sWs[c*64+lane+32];
            float wv0=sWv[c*64+lane], wv1=sWv[c*64+lane+32];
            float bs=stg[warp][c];
            a0 += bs*ws0; a1 += bs*ws1;
            #pragma unroll
            for (int i=0;i<3;i++){
                float bv = stg[warp][64+i*64+c];
                av[i][0]+=bv*wv0; av[i][1]+=bv*wv1;
            }
        }
        g_up[n*64+lane]    = make_float4(a0, av[0][0], av[1][0], av[2][0]);
        g_up[n*64+lane+32] = make_float4(a1, av[0][1], av[1][1], av[2][1]);
        __syncwarp();
    }
}

// ---------------- edge kernel: table lookup + messages + float4 scatter ----------------
__global__ __launch_bounds__(256) void k_edge(const float* __restrict__ tab,
                                              const int* __restrict__ eidx)
{
    int warp = threadIdx.x>>5, lane = threadIdx.x&31;
    int e = blockIdx.x*8 + warp;
    if (e >= EE) return;
    float4 yu = g_Y1u[e];
    float u = yu.w;
    if (u >= 1.0f) return;                       // env=0 -> w=0 -> no contribution (exact)
    float t = u * (float)(TT-1);
    int i0 = (int)t; if (i0 > TT-2) i0 = TT-2;
    float f = t - (float)i0;
    const float* r0 = tab + i0*320;
    int snd = __ldg(eidx + e);
    int rcv = __ldg(eidx + EE + e);

    const float IS3 = 0.5773502691896258f;
    const float IS2 = 0.7071067811865475f;
    const float IA  = 1.0f/32.0f;

    #pragma unroll
    for (int h=0; h<2; h++){
        int c = lane + h*32;
        float w[5];
        #pragma unroll
        for (int g=0; g<5; g++){
            float a = __ldg(r0 + g*64 + c);
            float b = __ldg(r0 + 320 + g*64 + c);
            w[g] = a + f*(b - a);
        }
        float4 up = __ldg(&g_up[snd*64 + c]);    // (sj, v0, v1, v2)
        float dv = up.y*yu.x + up.z*yu.y + up.w*yu.z;
        float m0 = (w[0]*up.x + w[1]*dv*IS3) * IA;
        float cx = up.z*yu.z - up.w*yu.y;
        float cy = up.w*yu.x - up.y*yu.z;
        float cz = up.y*yu.y - up.z*yu.x;
        float sy = w[2]*up.x;
        float wc = w[4]*IS2;
        float m1x = (sy*yu.x + w[3]*up.y + wc*cx) * IA;
        float m1y = (sy*yu.y + w[3]*up.z + wc*cy) * IA;
        float m1z = (sy*yu.z + w[3]*up.w + wc*cz) * IA;
        float* p = (float*)(g_agg + rcv*64 + c);
        asm volatile("red.global.add.v4.f32 [%0], {%1,%2,%3,%4};"
                     :: "l"(p), "f"(m0), "f"(m1x), "f"(m1y), "f"(m1z) : "memory");
    }
}

// ---------------- node update: out/sc/prod + write descriptor ----------------
#define NODE_SMEM_FLOATS (4*CC*CC + 8*768)

__global__ __launch_bounds__(256) void k_node(
    const float* __restrict__ attrs,
    const float* __restrict__ Wout_s, const float* __restrict__ Wout_v,
    const float* __restrict__ Wsc_s,  const float* __restrict__ Wsc_v,
    const float* __restrict__ P0,     const float* __restrict__ P1,
    const float* __restrict__ Wprod_s,const float* __restrict__ Wprod_v,
    float* __restrict__ outL)
{
    extern __shared__ float sm[];
    float* sWos = sm;
    float* sWov = sWos + 4096;
    float* sWps = sWov + 4096;
    float* sWpv = sWps + 4096;
    float* sStage = sWpv + 4096;
    int tid = threadIdx.x;
    for (int i=tid;i<4096;i+=blockDim.x){
        sWos[i]=Wout_s[i]; sWov[i]=Wout_v[i]; sWps[i]=Wprod_s[i]; sWpv[i]=Wprod_v[i];
    }
    __syncthreads();
    int warp = tid>>5, lane = tid&31;
    float* stg = sStage + warp*768;
    // stage: agg0 [0,64) agg1 [64,256) s [256,320) v [320,512) prodS [512,576) prodV [576,768)

    for (int n = blockIdx.x*8 + warp; n < NN; n += gridDim.x*8) {
        float av = (lane < ZZ) ? __ldg(attrs + n*ZZ + lane) : 0.f;
        unsigned msk = __ballot_sync(0xffffffffu, av > 0.5f);
        int z = __ffs(msk) - 1;

        float4 A = g_agg[n*64+lane];
        float4 B = g_agg[n*64+lane+32];
        stg[lane]        = A.x; stg[64+lane]     = A.y; stg[128+lane]    = A.z; stg[192+lane]    = A.w;
        stg[lane+32]     = B.x; stg[64+lane+32]  = B.y; stg[128+lane+32] = B.z; stg[192+lane+32] = B.w;
        stg[256+lane]    = g_s[n*64+lane];
        stg[256+lane+32] = g_s[n*64+lane+32];
        #pragma unroll
        for (int j=lane;j<192;j+=32) stg[320+j] = g_v[n*192+j];
        __syncwarp();

        const float* Wss = Wsc_s + (size_t)z*4096;
        const float* Wsv = Wsc_v + (size_t)z*4096;
        float ms0=0.f, ms1=0.f, scs0=0.f, scs1=0.f;
        float mv[3][2]={}, scv[3][2]={};
        #pragma unroll 4
        for (int c=0;c<64;c++){
            float a0 = stg[c];
            float sb = stg[256+c];
            float wos0=sWos[c*64+lane], wos1=sWos[c*64+lane+32];
            float wov0=sWov[c*64+lane], wov1=sWov[c*64+lane+32];
            float wss0=__ldg(Wss+c*64+lane), wss1=__ldg(Wss+c*64+lane+32);
            float wsv0=__ldg(Wsv+c*64+lane), wsv1=__ldg(Wsv+c*64+lane+32);
            ms0 += a0*wos0; ms1 += a0*wos1;
            scs0 += sb*wss0; scs1 += sb*wss1;
            #pragma unroll
            for (int i=0;i<3;i++){
                float a1 = stg[64+i*64+c];
                float vb = stg[320+i*64+c];
                mv[i][0]  += a1*wov0; mv[i][1]  += a1*wov1;
                scv[i][0] += vb*wsv0; scv[i][1] += vb*wsv1;
            }
        }

        const float* p0 = P0 + (size_t)z*CC*3;
        const float* q0 = P1 + (size_t)z*CC*2;
        float pa0=__ldg(p0+lane*3+0), pa1=__ldg(p0+lane*3+1), pa2=__ldg(p0+lane*3+2);
        float pb0=__ldg(p0+(lane+32)*3+0), pb1=__ldg(p0+(lane+32)*3+1), pb2=__ldg(p0+(lane+32)*3+2);
        float qa0=__ldg(q0+lane*2+0), qa1=__ldg(q0+lane*2+1);
        float qb0=__ldg(q0+(lane+32)*2+0), qb1=__ldg(q0+(lane+32)*2+1);

        float n2a = mv[0][0]*mv[0][0]+mv[1][0]*mv[1][0]+mv[2][0]*mv[2][0];
        float n2b = mv[0][1]*mv[0][1]+mv[1][1]*mv[1][1]+mv[2][1]*mv[2][1];
        stg[512+lane]    = pa0*ms0 + pa1*ms0*ms0 + pa2*n2a;
        stg[512+lane+32] = pb0*ms1 + pb1*ms1*ms1 + pb2*n2b;
        #pragma unroll
        for (int i=0;i<3;i++){
            stg[576+i*64+lane]    = qa0*mv[i][0] + qa1*ms0*mv[i][0];
            stg[576+i*64+lane+32] = qb0*mv[i][1] + qb1*ms1*mv[i][1];
        }
        __syncwarp();

        float sn0=scs0, sn1=scs1;
        float vn[3][2];
        #pragma unroll
        for (int i=0;i<3;i++){ vn[i][0]=scv[i][0]; vn[i][1]=scv[i][1]; }
        #pragma unroll 4
        for (int c=0;c<64;c++){
            float ps = stg[512+c];
            float wps0=sWps[c*64+lane], wps1=sWps[c*64+lane+32];
            float wpv0=sWpv[c*64+lane], wpv1=sWpv[c*64+lane+32];
            sn0 += ps*wps0; sn1 += ps*wps1;
            #pragma unroll
            for (int i=0;i<3;i++){
                float pv = stg[576+i*64+c];
                vn[i][0]+=pv*wpv0; vn[i][1]+=pv*wpv1;
            }
        }

        g_s[n*64+lane]=sn0; g_s[n*64+lane+32]=sn1;
        #pragma unroll
        for (int i=0;i<3;i++){
            g_v[n*192+i*64+lane]=vn[i][0];
            g_v[n*192+i*64+lane+32]=vn[i][1];
        }
        outL[n*128+lane]=sn0; outL[n*128+lane+32]=sn1;
        __syncwarp();
    }
}

// ---------------- launch ----------------
extern "C" void kernel_launch(void* const* d_in, const int* in_sizes, int n_in,
                              void* d_out, int out_size)
{
    const float* attrs   = (const float*)d_in[0];
    const float* pos     = (const float*)d_in[1];
    const float* shifts  = (const float*)d_in[2];
    const float* Wemb    = (const float*)d_in[3];
    const float* Wup_s   = (const float*)d_in[4];
    const float* Wup_v   = (const float*)d_in[5];
    const float* RW1     = (const float*)d_in[6];
    const float* RW2     = (const float*)d_in[7];
    const float* RW3     = (const float*)d_in[8];
    const float* Wout_s  = (const float*)d_in[9];
    const float* Wout_v  = (const float*)d_in[10];
    const float* Wsc_s   = (const float*)d_in[11];
    const float* Wsc_v   = (const float*)d_in[12];
    const float* P0      = (const float*)d_in[13];
    const float* P1      = (const float*)d_in[14];
    const float* Wprod_s = (const float*)d_in[15];
    const float* Wprod_v = (const float*)d_in[16];
    const int*   eidx    = (const int*)d_in[17];
    float* out = (float*)d_out;

    const int node_smem = NODE_SMEM_FLOATS * 4;
    cudaFuncSetAttribute(k_node, cudaFuncAttributeMaxDynamicSharedMemorySize, node_smem);

    k_geom<<<(EE+255)/256, 256>>>(pos, shifts, eidx);
    k_embed<<<(NN*CC+255)/256, 256>>>(attrs, Wemb);
    k_table<<<dim3(TT, LLAYERS), 64>>>(RW1, RW2, RW3);

    float* tab_base;
    cudaGetSymbolAddress((void**)&tab_base, g_tab);

    for (int layer=0; layer<LLAYERS; layer++){
        k_zero<<<512, 256>>>();
        k_up<<<592, 256>>>(Wup_s + layer*CC*CC, Wup_v + layer*CC*CC);
        k_edge<<<(EE+7)/8, 256>>>(tab_base + (size_t)layer*TT*5*CC, eidx);
        k_node<<<296, 256, node_smem>>>(
            attrs,
            Wout_s + layer*CC*CC, Wout_v + layer*CC*CC,
            Wsc_s + (size_t)layer*ZZ*CC*CC, Wsc_v + (size_t)layer*ZZ*CC*CC,
            P0 + (size_t)layer*ZZ*CC*3, P1 + (size_t)layer*ZZ*CC*2,
            Wprod_s + layer*CC*CC, Wprod_v + layer*CC*CC,
            out + layer*CC);
    }
}